// round 5
// baseline (speedup 1.0000x reference)
#include <cuda_runtime.h>
#include <math.h>

// ---------------- constants ----------------
#define PADK         68        // padded column stride (floats) -> conflict-free LDS.128
#define OFF_W0T      0
#define OFF_W1T      2176
#define OFF_W2T      4352
#define OFF_W3T      6528
#define OFF_WAT      8704
#define OFF_WBT      10880
#define OFF_WM1T     13056
#define OFF_WM2T     17408
#define OFF_WM3T     21760
#define WTOT         30464     // total weight floats in smem
#define NWARP        8
#define NPAIR        4         // row-pairs per warp (8 rows)
#define RS2          768       // floats per row-PAIR (interleaved)
// pair-local float offsets (each logical element is 2 floats: {rowA,rowB})
#define PS0          0         // s0: 64 elems  -> overlay m0
#define PS1          128       // s1: 192 elems ([k][u], k stride 128 floats) -> overlay m1
#define PT1          512       // t1: 64 elems  -> overlay ob (rowA at PT1, rowB at PT1+128)
#define PHB          640       // sc then hb: 64 elems
#define SMEM_FLOATS  (WTOT + NWARP * NPAIR * RS2)   // 30464 + 24576 = 55040
#define SMEM_BYTES   (SMEM_FLOATS * 4)              // 220160

__device__ float g_cst;
__device__ float g_wbuf[WTOT];

// ---------------- packed f32x2 helpers ----------------
typedef unsigned long long u64;
__device__ __forceinline__ u64 pk2(float lo, float hi) {
    u64 d; asm("mov.b64 %0,{%1,%2};" : "=l"(d) : "f"(lo), "f"(hi)); return d;
}
__device__ __forceinline__ u64 dup2(float w) {
    u64 d; asm("mov.b64 %0,{%1,%1};" : "=l"(d) : "f"(w)); return d;
}
__device__ __forceinline__ u64 f2fma(u64 a, u64 b, u64 c) {
    u64 d; asm("fma.rn.f32x2 %0,%1,%2,%3;" : "=l"(d) : "l"(a), "l"(b), "l"(c)); return d;
}
__device__ __forceinline__ u64 f2mul(u64 a, u64 b) {
    u64 d; asm("mul.rn.f32x2 %0,%1,%2;" : "=l"(d) : "l"(a), "l"(b)); return d;
}
__device__ __forceinline__ void upk2(u64 v, float& lo, float& hi) {
    asm("mov.b64 {%0,%1},%2;" : "=f"(lo), "=f"(hi) : "l"(v));
}

#define DUP4(nm, v4) u64 nm##x = dup2((v4).x), nm##y = dup2((v4).y), \
                         nm##z = dup2((v4).z), nm##w = dup2((v4).w)
#define FMA4(acc, t0, t1, W) do { \
    acc = f2fma((t0).x, W##x, acc); acc = f2fma((t0).y, W##y, acc); \
    acc = f2fma((t1).x, W##z, acc); acc = f2fma((t1).y, W##w, acc); } while (0)

// ---------------- prep: cst (block 0) + fold scales, merge Wl@Wf, transpose+pad ----------
__global__ void prep_kernel(const float* __restrict__ w0, const float* __restrict__ w1,
                            const float* __restrict__ w2, const float* __restrict__ w3,
                            const float* __restrict__ Wl0, const float* __restrict__ Wl1,
                            const float* __restrict__ Wm1, const float* __restrict__ Wm2,
                            const float* __restrict__ Wm3,
                            const float* __restrict__ Wf0, const float* __restrict__ Wf1) {
    if (blockIdx.x == 0) {
        const int   N = 20000;
        const float h = 24.0f / 20000.0f;
        float local = 0.0f;
        for (int i = threadIdx.x; i <= N; i += blockDim.x) {
            float z   = -12.0f + h * (float)i;
            float s   = z / (1.0f + __expf(-z));
            float phi = __expf(-0.5f * z * z) * 0.3989422804014327f;
            float f   = s * s * phi;
            if (i == 0 || i == N) f *= 0.5f;
            local += f;
        }
        __shared__ float red[256];
        red[threadIdx.x] = local;
        __syncthreads();
        for (int s = 128; s > 0; s >>= 1) {
            if (threadIdx.x < s) red[threadIdx.x] += red[threadIdx.x + s];
            __syncthreads();
        }
        if (threadIdx.x == 0) g_cst = rsqrtf(red[0] * h);
    }

    int tid = blockIdx.x * blockDim.x + threadIdx.x;
    if (tid >= 28672) return;
    const float INV_S3 = 0.57735026918962576f;
    const float WSCALE = 0.125f * 0.125f * 0.17677669529663687f;  // PW/(sqrt(U)*sqrt(MUL))

    if (tid < 12288) {                       // six (64,32) matrices
        int m = tid / 2048, r = tid % 2048;
        int i = r / 32, j = r % 32;
        float v; int off;
        if (m == 0)      { v = w0[i * 32 + j];           off = OFF_W0T; }
        else if (m == 1) { v = w1[i * 32 + j] * INV_S3;  off = OFF_W1T; }
        else if (m == 2) { v = w2[i * 32 + j];           off = OFF_W2T; }
        else if (m == 3) { v = w3[i * 32 + j];           off = OFF_W3T; }
        else {
            const float* L = (m == 4) ? Wl0 : Wl1;
            const float* F = (m == 4) ? Wf0 : Wf1;
            float acc = 0.0f;
            for (int w = 0; w < 32; w++) acc = fmaf(L[i * 32 + w], F[w * 32 + j], acc);
            v   = acc * WSCALE;
            off = (m == 4) ? OFF_WAT : OFF_WBT;
        }
        g_wbuf[off + j * PADK + i] = v;
    } else if (tid < 20480) {                // Wm1 / Wm2 (64,64), fold 1/8
        int t2 = tid - 12288;
        int mm = t2 / 4096, r = t2 % 4096;
        int i = r / 64, j = r % 64;
        const float* W = mm ? Wm2 : Wm1;
        g_wbuf[(mm ? OFF_WM2T : OFF_WM1T) + j * PADK + i] = W[i * 64 + j] * 0.125f;
    } else {                                 // Wm3 (64,128), fold 1/8
        int r = tid - 20480;
        int i = r / 128, j = r % 128;
        g_wbuf[OFF_WM3T + j * PADK + i] = Wm3[i * 128 + j] * 0.125f;
    }
}

// ---------------- main: warp = 4 row-pairs (8 rows), f32x2 packed math ----------------
__global__ __launch_bounds__(256, 1)
void tp_main_kernel(const float* __restrict__ x1a, const float* __restrict__ x1b,
                    const float4* __restrict__ x2, const float* __restrict__ scalars,
                    float* __restrict__ out, int nrows) {
    extern __shared__ float smem[];
    {
        const float4* src = (const float4*)g_wbuf;
        float4* dst = (float4*)smem;
        for (int i = threadIdx.x; i < WTOT / 4; i += blockDim.x) dst[i] = src[i];
    }
    __syncthreads();
    const float cst = g_cst;

    const int lid = threadIdx.x & 31;
    const int wid = threadIdx.x >> 5;

    float* Sw = smem + WTOT + wid * (NPAIR * RS2);

    const float* w0t  = smem + OFF_W0T;
    const float* w1t  = smem + OFF_W1T;
    const float* w2t  = smem + OFF_W2T;
    const float* w3t  = smem + OFF_W3T;
    const float* wat  = smem + OFF_WAT;
    const float* wbt  = smem + OFF_WBT;
    const float* wm1t = smem + OFF_WM1T;
    const float* wm2t = smem + OFF_WM2T;
    const float* wm3t = smem + OFF_WM3T;

    const int gstride = gridDim.x * NWARP * (2 * NPAIR);
    for (int e = (blockIdx.x * NWARP + wid) * (2 * NPAIR); e < nrows; e += gstride) {
        // ---- stage 8 rows (4 interleaved pairs); nrows % 8 == 0 ----
        float4 yv4[2 * NPAIR];
#pragma unroll
        for (int r = 0; r < 2 * NPAIR; r++) {
            int row = e + r;
            float* P = Sw + (r >> 1) * RS2;
            int h = r & 1;
            float4 va = ((const float4*)x1a)[row * 32 + lid];
            float4 vb = ((const float4*)x1b)[row * 32 + lid];
            yv4[r] = x2[row];
            if (lid < 16) {
                float4 s = ((const float4*)scalars)[row * 16 + lid];
                int b0 = PHB + 8 * lid + h;
                P[b0] = s.x; P[b0 + 2] = s.y; P[b0 + 4] = s.z; P[b0 + 6] = s.w;
            }
            if (lid < 8) {
                int b0 = PS0 + 8 * lid + h;
                P[b0] = va.x; P[b0 + 2] = va.y; P[b0 + 4] = va.z; P[b0 + 6] = va.w;
                int b1 = PS0 + 64 + 8 * lid + h;
                P[b1] = vb.x; P[b1 + 2] = vb.y; P[b1 + 4] = vb.z; P[b1 + 6] = vb.w;
            } else {
                int f = 4 * lid - 32;
                float av[4] = {va.x, va.y, va.z, va.w};
                float bv[4] = {vb.x, vb.y, vb.z, vb.w};
#pragma unroll
                for (int t = 0; t < 4; t++) {
                    int u = (f + t) / 3, k = (f + t) % 3;
                    P[PS1 + k * 128 + 2 * u + h]      = av[t];
                    P[PS1 + k * 128 + 64 + 2 * u + h] = bv[t];
                }
            }
        }
        __syncwarp();

        // ---- t1[u] = s1[u,:] . y1 (packed; Y packs recomputed on demand) ----
#pragma unroll
        for (int p = 0; p < NPAIR; p++) {
            float* P = Sw + p * RS2;
            u64 Y1 = pk2(yv4[2 * p].y, yv4[2 * p + 1].y);
            u64 Y2 = pk2(yv4[2 * p].z, yv4[2 * p + 1].z);
            u64 Y3 = pk2(yv4[2 * p].w, yv4[2 * p + 1].w);
            u64 a = f2mul(*(const u64*)&P[PS1 + 2 * lid], Y1);
            a = f2fma(*(const u64*)&P[PS1 + 128 + 2 * lid], Y2, a);
            a = f2fma(*(const u64*)&P[PS1 + 256 + 2 * lid], Y3, a);
            *(u64*)&P[PT1 + 2 * lid] = a;
            u64 b = f2mul(*(const u64*)&P[PS1 + 64 + 2 * lid], Y1);
            b = f2fma(*(const u64*)&P[PS1 + 192 + 2 * lid], Y2, b);
            b = f2fma(*(const u64*)&P[PS1 + 320 + 2 * lid], Y3, b);
            *(u64*)&P[PT1 + 64 + 2 * lid] = b;
        }

        // ---- MLP layer 1 ----
        {
            u64 a0[NPAIR] = {0, 0, 0, 0}, a1[NPAIR] = {0, 0, 0, 0};
#pragma unroll
            for (int i = 0; i < 64; i += 4) {
                float4 wa = *(const float4*)&wm1t[lid * PADK + i];
                float4 wb = *(const float4*)&wm1t[(lid + 32) * PADK + i];
                DUP4(WA, wa); DUP4(WB, wb);
#pragma unroll
                for (int p = 0; p < NPAIR; p++) {
                    const float* P = Sw + p * RS2;
                    ulonglong2 t0 = *(const ulonglong2*)&P[PHB + 2 * i];
                    ulonglong2 t1 = *(const ulonglong2*)&P[PHB + 2 * i + 4];
                    FMA4(a0[p], t0, t1, WA);
                    FMA4(a1[p], t0, t1, WB);
                }
            }
            __syncwarp();
#pragma unroll
            for (int p = 0; p < NPAIR; p++) {
                float* P = Sw + p * RS2;
                float l0, h0, l1, h1;
                upk2(a0[p], l0, h0); upk2(a1[p], l1, h1);
                l0 = cst * l0 / (1.0f + __expf(-l0)); h0 = cst * h0 / (1.0f + __expf(-h0));
                l1 = cst * l1 / (1.0f + __expf(-l1)); h1 = cst * h1 / (1.0f + __expf(-h1));
                *(u64*)&P[PHB + 2 * lid]      = pk2(l0, h0);
                *(u64*)&P[PHB + 64 + 2 * lid] = pk2(l1, h1);
            }
            __syncwarp();
        }

        // ---- MLP layer 2 ----
        {
            u64 a0[NPAIR] = {0, 0, 0, 0}, a1[NPAIR] = {0, 0, 0, 0};
#pragma unroll
            for (int i = 0; i < 64; i += 4) {
                float4 wa = *(const float4*)&wm2t[lid * PADK + i];
                float4 wb = *(const float4*)&wm2t[(lid + 32) * PADK + i];
                DUP4(WA, wa); DUP4(WB, wb);
#pragma unroll
                for (int p = 0; p < NPAIR; p++) {
                    const float* P = Sw + p * RS2;
                    ulonglong2 t0 = *(const ulonglong2*)&P[PHB + 2 * i];
                    ulonglong2 t1 = *(const ulonglong2*)&P[PHB + 2 * i + 4];
                    FMA4(a0[p], t0, t1, WA);
                    FMA4(a1[p], t0, t1, WB);
                }
            }
            __syncwarp();
#pragma unroll
            for (int p = 0; p < NPAIR; p++) {
                float* P = Sw + p * RS2;
                float l0, h0, l1, h1;
                upk2(a0[p], l0, h0); upk2(a1[p], l1, h1);
                l0 = cst * l0 / (1.0f + __expf(-l0)); h0 = cst * h0 / (1.0f + __expf(-h0));
                l1 = cst * l1 / (1.0f + __expf(-l1)); h1 = cst * h1 / (1.0f + __expf(-h1));
                *(u64*)&P[PHB + 2 * lid]      = pk2(l0, h0);
                *(u64*)&P[PHB + 64 + 2 * lid] = pk2(l1, h1);
            }
            __syncwarp();
        }

        // ---- MLP layer 3: weights[128] kept in registers (same-lane use only) ----
        u64 b0[NPAIR] = {0, 0, 0, 0}, b1[NPAIR] = {0, 0, 0, 0},
            b2[NPAIR] = {0, 0, 0, 0}, b3[NPAIR] = {0, 0, 0, 0};
#pragma unroll
        for (int i = 0; i < 64; i += 4) {
            float4 wv0 = *(const float4*)&wm3t[lid * PADK + i];
            float4 wv1 = *(const float4*)&wm3t[(lid + 32) * PADK + i];
            float4 wv2 = *(const float4*)&wm3t[(lid + 64) * PADK + i];
            float4 wv3 = *(const float4*)&wm3t[(lid + 96) * PADK + i];
            DUP4(W0, wv0); DUP4(W1, wv1); DUP4(W2, wv2); DUP4(W3, wv3);
#pragma unroll
            for (int p = 0; p < NPAIR; p++) {
                const float* P = Sw + p * RS2;
                ulonglong2 t0 = *(const ulonglong2*)&P[PHB + 2 * i];
                ulonglong2 t1 = *(const ulonglong2*)&P[PHB + 2 * i + 4];
                FMA4(b0[p], t0, t1, W0);
                FMA4(b1[p], t0, t1, W1);
                FMA4(b2[p], t0, t1, W2);
                FMA4(b3[p], t0, t1, W3);
            }
        }

        // ---- TP stage 1, loop A: r0 = s0@w0, p = s0@w2, r1 = t1@w1 ----
        u64 R0[NPAIR] = {0, 0, 0, 0}, PPa[NPAIR] = {0, 0, 0, 0}, R1[NPAIR] = {0, 0, 0, 0};
#pragma unroll
        for (int i = 0; i < 64; i += 4) {
            float4 w0v = *(const float4*)&w0t[lid * PADK + i];
            float4 w1v = *(const float4*)&w1t[lid * PADK + i];
            float4 w2v = *(const float4*)&w2t[lid * PADK + i];
            DUP4(W0, w0v); DUP4(W1, w1v); DUP4(W2, w2v);
#pragma unroll
            for (int p = 0; p < NPAIR; p++) {
                const float* P = Sw + p * RS2;
                ulonglong2 s0a = *(const ulonglong2*)&P[PS0 + 2 * i];
                ulonglong2 s0b = *(const ulonglong2*)&P[PS0 + 2 * i + 4];
                ulonglong2 t1a = *(const ulonglong2*)&P[PT1 + 2 * i];
                ulonglong2 t1b = *(const ulonglong2*)&P[PT1 + 2 * i + 4];
                FMA4(R0[p],  s0a, s0b, W0);
                FMA4(PPa[p], s0a, s0b, W2);
                FMA4(R1[p],  t1a, t1b, W1);
            }
        }
        // ---- TP stage 1, loop B: qk = s1k@w3 ----
        u64 Q0[NPAIR] = {0, 0, 0, 0}, Q1[NPAIR] = {0, 0, 0, 0}, Q2[NPAIR] = {0, 0, 0, 0};
#pragma unroll
        for (int i = 0; i < 64; i += 4) {
            float4 w3v = *(const float4*)&w3t[lid * PADK + i];
            DUP4(W3, w3v);
#pragma unroll
            for (int p = 0; p < NPAIR; p++) {
                const float* P = Sw + p * RS2;
                ulonglong2 u0a = *(const ulonglong2*)&P[PS1 + 2 * i];
                ulonglong2 u0b = *(const ulonglong2*)&P[PS1 + 2 * i + 4];
                ulonglong2 u1a = *(const ulonglong2*)&P[PS1 + 128 + 2 * i];
                ulonglong2 u1b = *(const ulonglong2*)&P[PS1 + 128 + 2 * i + 4];
                ulonglong2 u2a = *(const ulonglong2*)&P[PS1 + 256 + 2 * i];
                ulonglong2 u2b = *(const ulonglong2*)&P[PS1 + 256 + 2 * i + 4];
                FMA4(Q0[p], u0a, u0b, W3);
                FMA4(Q1[p], u1a, u1b, W3);
                FMA4(Q2[p], u2a, u2b, W3);
            }
        }
        __syncwarp();   // done reading s0/s1/t1 -> safe to overlay m0/m1

        // ---- build m0, m1 (packed; scales pre-folded) ----
#pragma unroll
        for (int p = 0; p < NPAIR; p++) {
            float* P = Sw + p * RS2;
            u64 Y0 = pk2(yv4[2 * p].x, yv4[2 * p + 1].x);
            u64 Y1 = pk2(yv4[2 * p].y, yv4[2 * p + 1].y);
            u64 Y2 = pk2(yv4[2 * p].z, yv4[2 * p + 1].z);
            u64 Y3 = pk2(yv4[2 * p].w, yv4[2 * p + 1].w);
            u64 pw   = f2mul(PPa[p], b2[p]);       // p * wt[64+lid]
            u64 y0wq = f2mul(Y0, b3[p]);           // y0 * wt[96+lid]
            *(u64*)&P[PS0 + 2 * lid]       = f2mul(f2mul(Y0, R0[p]), b0[p]);
            *(u64*)&P[PS0 + 64 + 2 * lid]  = f2mul(R1[p], b1[p]);
            *(u64*)&P[PS1 + 2 * lid]       = f2mul(Y1, pw);
            *(u64*)&P[PS1 + 64 + 2 * lid]  = f2mul(Q0[p], y0wq);
            *(u64*)&P[PS1 + 128 + 2 * lid] = f2mul(Y2, pw);
            *(u64*)&P[PS1 + 192 + 2 * lid] = f2mul(Q1[p], y0wq);
            *(u64*)&P[PS1 + 256 + 2 * lid] = f2mul(Y3, pw);
            *(u64*)&P[PS1 + 320 + 2 * lid] = f2mul(Q2[p], y0wq);
        }
        __syncwarp();

        // ---- final merged linears: o0 = m0@WA, o1k = m1k@WB ----
        u64 O0[NPAIR] = {0, 0, 0, 0}, O1[NPAIR] = {0, 0, 0, 0},
            O2[NPAIR] = {0, 0, 0, 0}, O3[NPAIR] = {0, 0, 0, 0};
#pragma unroll
        for (int i = 0; i < 64; i += 4) {
            float4 wav = *(const float4*)&wat[lid * PADK + i];
            float4 wbv = *(const float4*)&wbt[lid * PADK + i];
            DUP4(WA, wav); DUP4(WB, wbv);
#pragma unroll
            for (int p = 0; p < NPAIR; p++) {
                const float* P = Sw + p * RS2;
                ulonglong2 m0a = *(const ulonglong2*)&P[PS0 + 2 * i];
                ulonglong2 m0b = *(const ulonglong2*)&P[PS0 + 2 * i + 4];
                ulonglong2 k0a = *(const ulonglong2*)&P[PS1 + 2 * i];
                ulonglong2 k0b = *(const ulonglong2*)&P[PS1 + 2 * i + 4];
                ulonglong2 k1a = *(const ulonglong2*)&P[PS1 + 128 + 2 * i];
                ulonglong2 k1b = *(const ulonglong2*)&P[PS1 + 128 + 2 * i + 4];
                ulonglong2 k2a = *(const ulonglong2*)&P[PS1 + 256 + 2 * i];
                ulonglong2 k2b = *(const ulonglong2*)&P[PS1 + 256 + 2 * i + 4];
                FMA4(O0[p], m0a, m0b, WA);
                FMA4(O1[p], k0a, k0b, WB);
                FMA4(O2[p], k1a, k1b, WB);
                FMA4(O3[p], k2a, k2b, WB);
            }
        }
        __syncwarp();   // done reading m0/m1 -> safe to overlay ob

        // ---- stage + coalesced store ----
#pragma unroll
        for (int p = 0; p < NPAIR; p++) {
            float* obA = Sw + p * RS2 + PT1;
            float* obB = obA + 128;
            float xa, xb;
            upk2(O0[p], xa, xb); obA[lid] = xa;               obB[lid] = xb;
            upk2(O1[p], xa, xb); obA[32 + 3 * lid] = xa;      obB[32 + 3 * lid] = xb;
            upk2(O2[p], xa, xb); obA[33 + 3 * lid] = xa;      obB[33 + 3 * lid] = xb;
            upk2(O3[p], xa, xb); obA[34 + 3 * lid] = xa;      obB[34 + 3 * lid] = xb;
        }
        __syncwarp();
#pragma unroll
        for (int r = 0; r < 2 * NPAIR; r++) {
            const float* ob = Sw + (r >> 1) * RS2 + PT1 + (r & 1) * 128;
            ((float4*)out)[(e + r) * 32 + lid] = *(const float4*)&ob[4 * lid];
        }
        __syncwarp();
    }
}

// ---------------- launch ----------------
extern "C" void kernel_launch(void* const* d_in, const int* in_sizes, int n_in,
                              void* d_out, int out_size) {
    const float* x1a     = (const float*)d_in[0];
    const float* x1b     = (const float*)d_in[1];
    const float* x2      = (const float*)d_in[2];
    const float* scalars = (const float*)d_in[3];
    const float* w0      = (const float*)d_in[4];
    const float* w1      = (const float*)d_in[5];
    const float* w2      = (const float*)d_in[6];
    const float* w3      = (const float*)d_in[7];
    const float* Wl0     = (const float*)d_in[8];
    const float* Wl1     = (const float*)d_in[9];
    const float* Wm1     = (const float*)d_in[10];
    const float* Wm2     = (const float*)d_in[11];
    const float* Wm3     = (const float*)d_in[12];
    const float* Wf0     = (const float*)d_in[13];
    const float* Wf1     = (const float*)d_in[14];
    int n = in_sizes[0] / 128;

    cudaFuncSetAttribute(tp_main_kernel, cudaFuncAttributeMaxDynamicSharedMemorySize, SMEM_BYTES);

    prep_kernel<<<112, 256>>>(w0, w1, w2, w3, Wl0, Wl1, Wm1, Wm2, Wm3, Wf0, Wf1);
    tp_main_kernel<<<148, 256, SMEM_BYTES>>>(x1a, x1b, (const float4*)x2, scalars,
                                             (float*)d_out, n);
}

// round 6
// speedup vs baseline: 1.2756x; 1.2756x over previous
#include <cuda_runtime.h>
#include <math.h>

typedef unsigned int u32;

// fragment-linear weight buffer (floats)
#define FB_WM1 0
#define FB_WM2 4096
#define FB_WM3 8192
#define FB_W0  16384
#define FB_W1  18432
#define FB_W2  20480
#define FB_W3  22528
#define FB_WA  24576
#define FB_WB  26624
#define FB_TOT 28672

#define NWARP  6
#define TSTR   68
#define TFL    (16 * TSTR)          // 1088
#define OSTR   132
#define ARENA  (4 * TFL + 64)       // 4416
#define SMEM_FLOATS (FB_TOT + NWARP * ARENA)   // 55168
#define SMEM_BYTES  (SMEM_FLOATS * 4)          // 220672

__device__ float g_cst;
__device__ float g_wbuf[FB_TOT];

__device__ __forceinline__ u32 tf32(float f) {
    u32 u; asm("cvt.rna.tf32.f32 %0,%1;" : "=r"(u) : "f"(f)); return u;
}
__device__ __forceinline__ void split2(float x, u32& h, u32& l) {
    h = tf32(x);
    l = tf32(x - __uint_as_float(h));
}
__device__ __forceinline__ void mma_t(float* d, u32 a0, u32 a1, u32 a2, u32 a3,
                                      u32 b0, u32 b1) {
    asm("mma.sync.aligned.m16n8k8.row.col.f32.tf32.tf32.f32 "
        "{%0,%1,%2,%3},{%4,%5,%6,%7},{%8,%9},{%0,%1,%2,%3};"
        : "+f"(d[0]), "+f"(d[1]), "+f"(d[2]), "+f"(d[3])
        : "r"(a0), "r"(a1), "r"(a2), "r"(a3), "r"(b0), "r"(b1));
}

// acc[4*NT] += T[16x64] @ W ; A hi/lo-split, W fragment-linear single tf32
template<int NT>
__device__ __forceinline__ void gemm16s(float* acc, const float* T, const float* W,
                                        int r4, int m4, int lane) {
#pragma unroll
    for (int k8 = 0; k8 < 8; k8++) {
        const float* ap = T + r4 * TSTR + k8 * 8 + m4;
        u32 h0, l0, h1, l1, h2, l2, h3, l3;
        split2(ap[0], h0, l0);
        split2(ap[8 * TSTR], h1, l1);
        split2(ap[4], h2, l2);
        split2(ap[8 * TSTR + 4], h3, l3);
        const float* wp = W + k8 * NT * 64 + 2 * lane;
#pragma unroll
        for (int nt = 0; nt < NT; nt++) {
            uint2 b = *(const uint2*)(wp + nt * 64);
            mma_t(acc + 4 * nt, h0, h1, h2, h3, b.x, b.y);
            mma_t(acc + 4 * nt, l0, l1, l2, l3, b.x, b.y);
        }
    }
}

// ---------------- prep ----------------
__global__ void prep_kernel(const float* __restrict__ w0, const float* __restrict__ w1,
                            const float* __restrict__ w2, const float* __restrict__ w3,
                            const float* __restrict__ Wl0, const float* __restrict__ Wl1,
                            const float* __restrict__ Wm1, const float* __restrict__ Wm2,
                            const float* __restrict__ Wm3,
                            const float* __restrict__ Wf0, const float* __restrict__ Wf1) {
    if (blockIdx.x == 0) {
        const int   N = 20000;
        const float h = 24.0f / 20000.0f;
        float local = 0.0f;
        for (int i = threadIdx.x; i <= N; i += blockDim.x) {
            float z   = -12.0f + h * (float)i;
            float s   = z / (1.0f + __expf(-z));
            float phi = __expf(-0.5f * z * z) * 0.3989422804014327f;
            float f   = s * s * phi;
            if (i == 0 || i == N) f *= 0.5f;
            local += f;
        }
        __shared__ float red[256];
        red[threadIdx.x] = local;
        __syncthreads();
        for (int s = 128; s > 0; s >>= 1) {
            if (threadIdx.x < s) red[threadIdx.x] += red[threadIdx.x + s];
            __syncthreads();
        }
        if (threadIdx.x == 0) g_cst = rsqrtf(red[0] * h);
    }

    int tid = blockIdx.x * blockDim.x + threadIdx.x;
    if (tid >= FB_TOT) return;
    const float INV_S3 = 0.57735026918962576f;
    const float WSCALE = 0.125f * 0.125f * 0.17677669529663687f;

    int mbase, N;
    if (tid < 4096)       { mbase = 0;     N = 64; }
    else if (tid < 8192)  { mbase = 4096;  N = 64; }
    else if (tid < 16384) { mbase = 8192;  N = 128; }
    else                  { mbase = 16384 + ((tid - 16384) / 2048) * 2048; N = 32; }
    int idx = tid - mbase;
    int g = idx >> 6, pos = idx & 63, l = pos >> 1, hh = pos & 1;
    int ntn = N >> 3, k8 = g / ntn, n8 = g % ntn;
    int row = k8 * 8 + (l & 3) + 4 * hh;   // K index
    int col = n8 * 8 + (l >> 2);           // N index

    float v;
    if (tid < 4096)       v = Wm1[row * 64 + col] * 0.125f;
    else if (tid < 8192)  v = Wm2[row * 64 + col] * 0.125f;
    else if (tid < 16384) v = Wm3[row * 128 + col] * 0.125f;
    else if (tid < 18432) v = w0[row * 32 + col];
    else if (tid < 20480) v = w1[row * 32 + col] * INV_S3;
    else if (tid < 22528) v = w2[row * 32 + col];
    else if (tid < 24576) v = w3[row * 32 + col];
    else {
        const float* L = (tid < 26624) ? Wl0 : Wl1;
        const float* F = (tid < 26624) ? Wf0 : Wf1;
        float acc = 0.0f;
        for (int w = 0; w < 32; w++) acc = fmaf(L[row * 32 + w], F[w * 32 + col], acc);
        v = acc * WSCALE;
    }
    g_wbuf[tid] = __uint_as_float(tf32(v));
}

// ---------------- main ----------------
__global__ __launch_bounds__(192, 1)
void tp_mma_kernel(const float* __restrict__ x1a, const float* __restrict__ x1b,
                   const float4* __restrict__ x2, const float* __restrict__ scalars,
                   float* __restrict__ out, int nrows) {
    extern __shared__ float smem[];
    {
        const float4* src = (const float4*)g_wbuf;
        float4* dst = (float4*)smem;
        for (int i = threadIdx.x; i < FB_TOT / 4; i += 192) dst[i] = src[i];
    }
    __syncthreads();
    const float cst = g_cst;

    const int lane = threadIdx.x & 31, wid = threadIdx.x >> 5;
    const int r4 = lane >> 2, m4 = lane & 3;

    float* A0 = smem + FB_TOT + wid * ARENA;
    float* A1 = A0 + TFL;
    float* A2 = A1 + TFL;
    float* A3 = A2 + TFL;
    float* Yt = A3 + TFL;

    const int gw = blockIdx.x * NWARP + wid, gwn = gridDim.x * NWARP;
    const int ntiles = nrows >> 4;

    for (int t = gw; t < ntiles; t += gwn) {
        const int base = t * 16;

        // ---- stage scalars (fp32) + y ----
#pragma unroll
        for (int j = 0; j < 8; j++) {
            int row = r4 + 8 * (j & 1), f4 = m4 + 4 * (j >> 1);
            *(float4*)&A0[row * TSTR + 4 * f4] =
                ((const float4*)scalars)[(base + row) * 16 + f4];
        }
        if (lane < 16) *(float4*)&Yt[4 * lane] = x2[base + lane];
        __syncwarp();

        // ---- MLP GEMM1 -> silu -> GEMM2 -> silu -> GEMM3 ----
        float h[32];
#pragma unroll
        for (int i = 0; i < 32; i++) h[i] = 0.f;
        gemm16s<8>(h, A0, smem + FB_WM1, r4, m4, lane);
        __syncwarp();
#pragma unroll
        for (int nt = 0; nt < 8; nt++) {
            float a = h[4 * nt],     b = h[4 * nt + 1];
            float c = h[4 * nt + 2], d = h[4 * nt + 3];
            float2 lo = {cst * a / (1.f + __expf(-a)), cst * b / (1.f + __expf(-b))};
            float2 hi = {cst * c / (1.f + __expf(-c)), cst * d / (1.f + __expf(-d))};
            *(float2*)&A0[r4 * TSTR + nt * 8 + 2 * m4]       = lo;
            *(float2*)&A0[(r4 + 8) * TSTR + nt * 8 + 2 * m4] = hi;
        }
        __syncwarp();
#pragma unroll
        for (int i = 0; i < 32; i++) h[i] = 0.f;
        gemm16s<8>(h, A0, smem + FB_WM2, r4, m4, lane);
        __syncwarp();
#pragma unroll
        for (int nt = 0; nt < 8; nt++) {
            float a = h[4 * nt],     b = h[4 * nt + 1];
            float c = h[4 * nt + 2], d = h[4 * nt + 3];
            float2 lo = {cst * a / (1.f + __expf(-a)), cst * b / (1.f + __expf(-b))};
            float2 hi = {cst * c / (1.f + __expf(-c)), cst * d / (1.f + __expf(-d))};
            *(float2*)&A0[r4 * TSTR + nt * 8 + 2 * m4]       = lo;
            *(float2*)&A0[(r4 + 8) * TSTR + nt * 8 + 2 * m4] = hi;
        }
        __syncwarp();
        float wt[64];
#pragma unroll
        for (int i = 0; i < 64; i++) wt[i] = 0.f;
        gemm16s<16>(wt, A0, smem + FB_WM3, r4, m4, lane);
        __syncwarp();

        // ---- stage x1 -> s0 (A0), s1k (A1..A3), fp32 ----
        for (int rr = 0; rr < 16; rr++) {
            float4 va = ((const float4*)x1a)[(base + rr) * 32 + lane];
            float4 vb = ((const float4*)x1b)[(base + rr) * 32 + lane];
            if (lane < 8) {
                *(float4*)&A0[rr * TSTR + 4 * lane]      = va;
                *(float4*)&A0[rr * TSTR + 32 + 4 * lane] = vb;
            } else {
                int f = 4 * lane - 32;
                float av[4] = {va.x, va.y, va.z, va.w};
                float bv[4] = {vb.x, vb.y, vb.z, vb.w};
#pragma unroll
                for (int q = 0; q < 4; q++) {
                    int u = (f + q) / 3, k = (f + q) % 3;
                    float* Tk = (k == 0) ? A1 : ((k == 1) ? A2 : A3);
                    Tk[rr * TSTR + u]      = av[q];
                    Tk[rr * TSTR + 32 + u] = bv[q];
                }
            }
        }
        __syncwarp();

        const float y0A = Yt[4 * r4],        y0B = Yt[4 * (r4 + 8)];
        const float yA1 = Yt[4 * r4 + 1],    yB1 = Yt[4 * (r4 + 8) + 1];
        const float yA2 = Yt[4 * r4 + 2],    yB2 = Yt[4 * (r4 + 8) + 2];
        const float yA3 = Yt[4 * r4 + 3],    yB3 = Yt[4 * (r4 + 8) + 3];

        // ---- G4/G5: R0 = s0@w0, Pp = s0@w2 (shared A frags) ----
        float R0[16], Pp[16], R1[16];
#pragma unroll
        for (int i = 0; i < 16; i++) { R0[i] = 0.f; Pp[i] = 0.f; R1[i] = 0.f; }
#pragma unroll
        for (int k8 = 0; k8 < 8; k8++) {
            const float* ap = A0 + r4 * TSTR + k8 * 8 + m4;
            u32 h0, l0, h1, l1, h2, l2, h3, l3;
            split2(ap[0], h0, l0);
            split2(ap[8 * TSTR], h1, l1);
            split2(ap[4], h2, l2);
            split2(ap[8 * TSTR + 4], h3, l3);
            const float* w0p = smem + FB_W0 + k8 * 4 * 64 + 2 * lane;
            const float* w2p = smem + FB_W2 + k8 * 4 * 64 + 2 * lane;
#pragma unroll
            for (int nt = 0; nt < 4; nt++) {
                uint2 b0 = *(const uint2*)(w0p + nt * 64);
                mma_t(R0 + 4 * nt, h0, h1, h2, h3, b0.x, b0.y);
                mma_t(R0 + 4 * nt, l0, l1, l2, l3, b0.x, b0.y);
                uint2 b2 = *(const uint2*)(w2p + nt * 64);
                mma_t(Pp + 4 * nt, h0, h1, h2, h3, b2.x, b2.y);
                mma_t(Pp + 4 * nt, l0, l1, l2, l3, b2.x, b2.y);
            }
        }

        // ---- G6: R1 = t1@w1, t1 frags built on the fly ----
#pragma unroll
        for (int k8 = 0; k8 < 8; k8++) {
            int o = r4 * TSTR + k8 * 8 + m4;
            float t0 = A1[o] * yA1 + A2[o] * yA2 + A3[o] * yA3;
            float t2 = A1[o + 4] * yA1 + A2[o + 4] * yA2 + A3[o + 4] * yA3;
            float t1v = A1[o + 8 * TSTR] * yB1 + A2[o + 8 * TSTR] * yB2 + A3[o + 8 * TSTR] * yB3;
            float t3 = A1[o + 8 * TSTR + 4] * yB1 + A2[o + 8 * TSTR + 4] * yB2 + A3[o + 8 * TSTR + 4] * yB3;
            u32 h0, l0, h1, l1, h2, l2, h3, l3;
            split2(t0, h0, l0); split2(t1v, h1, l1);
            split2(t2, h2, l2); split2(t3, h3, l3);
            const float* w1p = smem + FB_W1 + k8 * 4 * 64 + 2 * lane;
#pragma unroll
            for (int nt = 0; nt < 4; nt++) {
                uint2 b = *(const uint2*)(w1p + nt * 64);
                mma_t(R1 + 4 * nt, h0, h1, h2, h3, b.x, b.y);
                mma_t(R1 + 4 * nt, l0, l1, l2, l3, b.x, b.y);
            }
        }
        __syncwarp();   // s0 reads done -> overlay m0 on A0

        // ---- m0 build -> A0 ----
#pragma unroll
        for (int nt = 0; nt < 4; nt++) {
            A0[r4 * TSTR + nt * 8 + 2 * m4]           = y0A * R0[4 * nt]     * wt[4 * nt];
            A0[r4 * TSTR + nt * 8 + 2 * m4 + 1]       = y0A * R0[4 * nt + 1] * wt[4 * nt + 1];
            A0[(r4 + 8) * TSTR + nt * 8 + 2 * m4]     = y0B * R0[4 * nt + 2] * wt[4 * nt + 2];
            A0[(r4 + 8) * TSTR + nt * 8 + 2 * m4 + 1] = y0B * R0[4 * nt + 3] * wt[4 * nt + 3];
            int wi = 4 * (nt + 4);
            A0[r4 * TSTR + 32 + nt * 8 + 2 * m4]           = R1[4 * nt]     * wt[wi];
            A0[r4 * TSTR + 32 + nt * 8 + 2 * m4 + 1]       = R1[4 * nt + 1] * wt[wi + 1];
            A0[(r4 + 8) * TSTR + 32 + nt * 8 + 2 * m4]     = R1[4 * nt + 2] * wt[wi + 2];
            A0[(r4 + 8) * TSTR + 32 + nt * 8 + 2 * m4 + 1] = R1[4 * nt + 3] * wt[wi + 3];
        }

        // ---- G7: Qk = s1k@w3 (B shared across k) ----
        float Q[48];
#pragma unroll
        for (int i = 0; i < 48; i++) Q[i] = 0.f;
#pragma unroll
        for (int k8 = 0; k8 < 8; k8++) {
            u32 H[3][4], L[3][4];
#pragma unroll
            for (int k = 0; k < 3; k++) {
                const float* Tk = (k == 0) ? A1 : ((k == 1) ? A2 : A3);
                int o = r4 * TSTR + k8 * 8 + m4;
                split2(Tk[o], H[k][0], L[k][0]);
                split2(Tk[o + 8 * TSTR], H[k][1], L[k][1]);
                split2(Tk[o + 4], H[k][2], L[k][2]);
                split2(Tk[o + 8 * TSTR + 4], H[k][3], L[k][3]);
            }
            const float* w3p = smem + FB_W3 + k8 * 4 * 64 + 2 * lane;
#pragma unroll
            for (int nt = 0; nt < 4; nt++) {
                uint2 b = *(const uint2*)(w3p + nt * 64);
#pragma unroll
                for (int k = 0; k < 3; k++) {
                    mma_t(Q + 16 * k + 4 * nt, H[k][0], H[k][1], H[k][2], H[k][3], b.x, b.y);
                    mma_t(Q + 16 * k + 4 * nt, L[k][0], L[k][1], L[k][2], L[k][3], b.x, b.y);
                }
            }
        }
        __syncwarp();   // s1 reads done -> overlay m1k

        // ---- m1k build -> A1..A3 ----
#pragma unroll
        for (int k = 0; k < 3; k++) {
            float* Tk = (k == 0) ? A1 : ((k == 1) ? A2 : A3);
            float ykA = (k == 0) ? yA1 : ((k == 1) ? yA2 : yA3);
            float ykB = (k == 0) ? yB1 : ((k == 1) ? yB2 : yB3);
#pragma unroll
            for (int nt = 0; nt < 4; nt++) {
                int wi = 4 * (nt + 8), wj = 4 * (nt + 12);
                Tk[r4 * TSTR + nt * 8 + 2 * m4]           = ykA * Pp[4 * nt]     * wt[wi];
                Tk[r4 * TSTR + nt * 8 + 2 * m4 + 1]       = ykA * Pp[4 * nt + 1] * wt[wi + 1];
                Tk[(r4 + 8) * TSTR + nt * 8 + 2 * m4]     = ykB * Pp[4 * nt + 2] * wt[wi + 2];
                Tk[(r4 + 8) * TSTR + nt * 8 + 2 * m4 + 1] = ykB * Pp[4 * nt + 3] * wt[wi + 3];
                Tk[r4 * TSTR + 32 + nt * 8 + 2 * m4]           = y0A * Q[16 * k + 4 * nt]     * wt[wj];
                Tk[r4 * TSTR + 32 + nt * 8 + 2 * m4 + 1]       = y0A * Q[16 * k + 4 * nt + 1] * wt[wj + 1];
                Tk[(r4 + 8) * TSTR + 32 + nt * 8 + 2 * m4]     = y0B * Q[16 * k + 4 * nt + 2] * wt[wj + 2];
                Tk[(r4 + 8) * TSTR + 32 + nt * 8 + 2 * m4 + 1] = y0B * Q[16 * k + 4 * nt + 3] * wt[wj + 3];
            }
        }
        __syncwarp();

        // ---- G8: O0 = m0@WA ; G9: Ok = m1k@WB (B shared) ----
        float O0[16];
#pragma unroll
        for (int i = 0; i < 16; i++) O0[i] = 0.f;
        gemm16s<4>(O0, A0, smem + FB_WA, r4, m4, lane);

        float O[48];
#pragma unroll
        for (int i = 0; i < 48; i++) O[i] = 0.f;
#pragma unroll
        for (int k8 = 0; k8 < 8; k8++) {
            u32 H[3][4], L[3][4];
#pragma unroll
            for (int k = 0; k < 3; k++) {
                const float* Tk = (k == 0) ? A1 : ((k == 1) ? A2 : A3);
                int o = r4 * TSTR + k8 * 8 + m4;
                split2(Tk[o], H[k][0], L[k][0]);
                split2(Tk[o + 8 * TSTR], H[k][1], L[k][1]);
                split2(Tk[o + 4], H[k][2], L[k][2]);
                split2(Tk[o + 8 * TSTR + 4], H[k][3], L[k][3]);
            }
            const float* wbp = smem + FB_WB + k8 * 4 * 64 + 2 * lane;
#pragma unroll
            for (int nt = 0; nt < 4; nt++) {
                uint2 b = *(const uint2*)(wbp + nt * 64);
#pragma unroll
                for (int k = 0; k < 3; k++) {
                    mma_t(O + 16 * k + 4 * nt, H[k][0], H[k][1], H[k][2], H[k][3], b.x, b.y);
                    mma_t(O + 16 * k + 4 * nt, L[k][0], L[k][1], L[k][2], L[k][3], b.x, b.y);
                }
            }
        }
        __syncwarp();   // m reads done -> overlay out staging on A0/A1

        // ---- stage outputs (OB = A0, stride OSTR) ----
        float* OB = A0;
#pragma unroll
        for (int nt = 0; nt < 4; nt++) {
            int u = nt * 8 + 2 * m4;
            OB[r4 * OSTR + u]           = O0[4 * nt];
            OB[r4 * OSTR + u + 1]       = O0[4 * nt + 1];
            OB[(r4 + 8) * OSTR + u]     = O0[4 * nt + 2];
            OB[(r4 + 8) * OSTR + u + 1] = O0[4 * nt + 3];
#pragma unroll
            for (int k = 0; k < 3; k++) {
                int c = 32 + 3 * u + k;
                OB[r4 * OSTR + c]           = O[16 * k + 4 * nt];
                OB[r4 * OSTR + c + 3]       = O[16 * k + 4 * nt + 1];
                OB[(r4 + 8) * OSTR + c]     = O[16 * k + 4 * nt + 2];
                OB[(r4 + 8) * OSTR + c + 3] = O[16 * k + 4 * nt + 3];
            }
        }
        __syncwarp();
#pragma unroll
        for (int rr = 0; rr < 16; rr++)
            ((float4*)out)[(base + rr) * 32 + lane] = *(const float4*)&OB[rr * OSTR + 4 * lane];
        __syncwarp();
    }
}

// ---------------- launch ----------------
extern "C" void kernel_launch(void* const* d_in, const int* in_sizes, int n_in,
                              void* d_out, int out_size) {
    const float* x1a     = (const float*)d_in[0];
    const float* x1b     = (const float*)d_in[1];
    const float* x2      = (const float*)d_in[2];
    const float* scalars = (const float*)d_in[3];
    const float* w0      = (const float*)d_in[4];
    const float* w1      = (const float*)d_in[5];
    const float* w2      = (const float*)d_in[6];
    const float* w3      = (const float*)d_in[7];
    const float* Wl0     = (const float*)d_in[8];
    const float* Wl1     = (const float*)d_in[9];
    const float* Wm1     = (const float*)d_in[10];
    const float* Wm2     = (const float*)d_in[11];
    const float* Wm3     = (const float*)d_in[12];
    const float* Wf0     = (const float*)d_in[13];
    const float* Wf1     = (const float*)d_in[14];
    int n = in_sizes[0] / 128;

    cudaFuncSetAttribute(tp_mma_kernel, cudaFuncAttributeMaxDynamicSharedMemorySize, SMEM_BYTES);

    prep_kernel<<<112, 256>>>(w0, w1, w2, w3, Wl0, Wl1, Wm1, Wm2, Wm3, Wf0, Wf1);
    tp_mma_kernel<<<148, 192, SMEM_BYTES>>>(x1a, x1b, (const float4*)x2, scalars,
                                            (float*)d_out, n);
}

// round 7
// speedup vs baseline: 1.5311x; 1.2003x over previous
#include <cuda_runtime.h>
#include <math.h>

typedef unsigned int u32;

// fragment-linear weight buffer (floats).  Wm3 lives at the END and stays in GLOBAL.
#define FB_WM1 0
#define FB_WM2 4096
#define FB_W0  8192
#define FB_W1  10240
#define FB_W2  12288
#define FB_W3  14336
#define FB_WA  16384
#define FB_WB  18432
#define FB_SM  20480               // floats copied to smem
#define FB_WM3 20480               // global-only (8192 floats)
#define FB_TOT 28672

#define NWARP  8
#define TSTR   68
#define TFL    (16 * TSTR)          // 1088
#define OSTR   132
#define ARENA  (4 * TFL + 64)       // 4416
#define SMEM_FLOATS (FB_SM + NWARP * ARENA)    // 20480 + 35328 = 55808
#define SMEM_BYTES  (SMEM_FLOATS * 4)          // 223232

__device__ float g_cst;
__device__ float g_wbuf[FB_TOT];

__device__ __forceinline__ u32 tf32(float f) {
    u32 u; asm("cvt.rna.tf32.f32 %0,%1;" : "=r"(u) : "f"(f)); return u;
}
__device__ __forceinline__ void split2(float x, u32& h, u32& l) {
    h = tf32(x);
    l = tf32(x - __uint_as_float(h));
}
__device__ __forceinline__ void mma_t(float* d, u32 a0, u32 a1, u32 a2, u32 a3,
                                      u32 b0, u32 b1) {
    asm("mma.sync.aligned.m16n8k8.row.col.f32.tf32.tf32.f32 "
        "{%0,%1,%2,%3},{%4,%5,%6,%7},{%8,%9},{%0,%1,%2,%3};"
        : "+f"(d[0]), "+f"(d[1]), "+f"(d[2]), "+f"(d[3])
        : "r"(a0), "r"(a1), "r"(a2), "r"(a3), "r"(b0), "r"(b1));
}

// acc[4*NT] += T[16x64] @ W(smem) ; A hi/lo-split, W fragment-linear single tf32
template<int NT>
__device__ __forceinline__ void gemm16s(float* acc, const float* T, const float* W,
                                        int r4, int m4, int lane) {
#pragma unroll
    for (int k8 = 0; k8 < 8; k8++) {
        const float* ap = T + r4 * TSTR + k8 * 8 + m4;
        u32 h0, l0, h1, l1, h2, l2, h3, l3;
        split2(ap[0], h0, l0);
        split2(ap[8 * TSTR], h1, l1);
        split2(ap[4], h2, l2);
        split2(ap[8 * TSTR + 4], h3, l3);
        const float* wp = W + k8 * NT * 64 + 2 * lane;
#pragma unroll
        for (int nt = 0; nt < NT; nt++) {
            uint2 b = *(const uint2*)(wp + nt * 64);
            mma_t(acc + 4 * nt, h0, h1, h2, h3, b.x, b.y);
            mma_t(acc + 4 * nt, l0, l1, l2, l3, b.x, b.y);
        }
    }
}

// same but W read from GLOBAL via __ldg (Wm3)
template<int NT>
__device__ __forceinline__ void gemm16g(float* acc, const float* T, const float* W,
                                        int r4, int m4, int lane) {
#pragma unroll
    for (int k8 = 0; k8 < 8; k8++) {
        const float* ap = T + r4 * TSTR + k8 * 8 + m4;
        u32 h0, l0, h1, l1, h2, l2, h3, l3;
        split2(ap[0], h0, l0);
        split2(ap[8 * TSTR], h1, l1);
        split2(ap[4], h2, l2);
        split2(ap[8 * TSTR + 4], h3, l3);
        const float* wp = W + k8 * NT * 64 + 2 * lane;
#pragma unroll
        for (int nt = 0; nt < NT; nt++) {
            uint2 b = __ldg((const uint2*)(wp + nt * 64));
            mma_t(acc + 4 * nt, h0, h1, h2, h3, b.x, b.y);
            mma_t(acc + 4 * nt, l0, l1, l2, l3, b.x, b.y);
        }
    }
}

// ---------------- prep ----------------
__global__ void prep_kernel(const float* __restrict__ w0, const float* __restrict__ w1,
                            const float* __restrict__ w2, const float* __restrict__ w3,
                            const float* __restrict__ Wl0, const float* __restrict__ Wl1,
                            const float* __restrict__ Wm1, const float* __restrict__ Wm2,
                            const float* __restrict__ Wm3,
                            const float* __restrict__ Wf0, const float* __restrict__ Wf1) {
    if (blockIdx.x == 0) {
        const int   N = 20000;
        const float h = 24.0f / 20000.0f;
        float local = 0.0f;
        for (int i = threadIdx.x; i <= N; i += blockDim.x) {
            float z   = -12.0f + h * (float)i;
            float s   = z / (1.0f + __expf(-z));
            float phi = __expf(-0.5f * z * z) * 0.3989422804014327f;
            float f   = s * s * phi;
            if (i == 0 || i == N) f *= 0.5f;
            local += f;
        }
        __shared__ float red[256];
        red[threadIdx.x] = local;
        __syncthreads();
        for (int s = 128; s > 0; s >>= 1) {
            if (threadIdx.x < s) red[threadIdx.x] += red[threadIdx.x + s];
            __syncthreads();
        }
        if (threadIdx.x == 0) g_cst = rsqrtf(red[0] * h);
    }

    int tid = blockIdx.x * blockDim.x + threadIdx.x;
    if (tid >= FB_TOT) return;
    const float INV_S3 = 0.57735026918962576f;
    const float WSCALE = 0.125f * 0.125f * 0.17677669529663687f;

    int mbase, N;
    if (tid < 4096)       { mbase = 0;     N = 64; }
    else if (tid < 8192)  { mbase = 4096;  N = 64; }
    else if (tid < 20480) { mbase = 8192 + ((tid - 8192) / 2048) * 2048; N = 32; }
    else                  { mbase = 20480; N = 128; }
    int idx = tid - mbase;
    int g = idx >> 6, pos = idx & 63, l = pos >> 1, hh = pos & 1;
    int ntn = N >> 3, k8 = g / ntn, n8 = g % ntn;
    int row = k8 * 8 + (l & 3) + 4 * hh;   // K index
    int col = n8 * 8 + (l >> 2);           // N index

    float v;
    if (tid < 4096)        v = Wm1[row * 64 + col] * 0.125f;
    else if (tid < 8192)   v = Wm2[row * 64 + col] * 0.125f;
    else if (tid < 20480) {
        int m = (tid - 8192) / 2048;
        if (m == 0)      v = w0[row * 32 + col];
        else if (m == 1) v = w1[row * 32 + col] * INV_S3;
        else if (m == 2) v = w2[row * 32 + col];
        else if (m == 3) v = w3[row * 32 + col];
        else {
            const float* L = (m == 4) ? Wl0 : Wl1;
            const float* F = (m == 4) ? Wf0 : Wf1;
            float acc = 0.0f;
            for (int w = 0; w < 32; w++) acc = fmaf(L[row * 32 + w], F[w * 32 + col], acc);
            v = acc * WSCALE;
        }
    } else                 v = Wm3[row * 128 + col] * 0.125f;
    g_wbuf[tid] = __uint_as_float(tf32(v));
}

// ---------------- main ----------------
__global__ __launch_bounds__(256, 1)
void tp_mma_kernel(const float* __restrict__ x1a, const float* __restrict__ x1b,
                   const float4* __restrict__ x2, const float* __restrict__ scalars,
                   float* __restrict__ out, int nrows) {
    extern __shared__ float smem[];
    {
        const float4* src = (const float4*)g_wbuf;
        float4* dst = (float4*)smem;
        for (int i = threadIdx.x; i < FB_SM / 4; i += 256) dst[i] = src[i];
    }
    __syncthreads();
    const float cst = g_cst;
    const float* wm3g = g_wbuf + FB_WM3;

    const int lane = threadIdx.x & 31, wid = threadIdx.x >> 5;
    const int r4 = lane >> 2, m4 = lane & 3;

    float* A0 = smem + FB_SM + wid * ARENA;
    float* A1 = A0 + TFL;
    float* A2 = A1 + TFL;
    float* A3 = A2 + TFL;
    float* Yt = A3 + TFL;

    const int gw = blockIdx.x * NWARP + wid, gwn = gridDim.x * NWARP;
    const int ntiles = nrows >> 4;

    for (int t = gw; t < ntiles; t += gwn) {
        const int base = t * 16;

        // ---- stage scalars (fp32) + y ----
#pragma unroll
        for (int j = 0; j < 8; j++) {
            int row = r4 + 8 * (j & 1), f4 = m4 + 4 * (j >> 1);
            *(float4*)&A0[row * TSTR + 4 * f4] =
                ((const float4*)scalars)[(base + row) * 16 + f4];
        }
        if (lane < 16) *(float4*)&Yt[4 * lane] = x2[base + lane];
        __syncwarp();

        // ---- MLP GEMM1 -> silu -> GEMM2 -> silu -> GEMM3 ----
        float h[32];
#pragma unroll
        for (int i = 0; i < 32; i++) h[i] = 0.f;
        gemm16s<8>(h, A0, smem + FB_WM1, r4, m4, lane);
        __syncwarp();
#pragma unroll
        for (int nt = 0; nt < 8; nt++) {
            float a = h[4 * nt],     b = h[4 * nt + 1];
            float c = h[4 * nt + 2], d = h[4 * nt + 3];
            float2 lo = {cst * a / (1.f + __expf(-a)), cst * b / (1.f + __expf(-b))};
            float2 hi = {cst * c / (1.f + __expf(-c)), cst * d / (1.f + __expf(-d))};
            *(float2*)&A0[r4 * TSTR + nt * 8 + 2 * m4]       = lo;
            *(float2*)&A0[(r4 + 8) * TSTR + nt * 8 + 2 * m4] = hi;
        }
        __syncwarp();
#pragma unroll
        for (int i = 0; i < 32; i++) h[i] = 0.f;
        gemm16s<8>(h, A0, smem + FB_WM2, r4, m4, lane);
        __syncwarp();
#pragma unroll
        for (int nt = 0; nt < 8; nt++) {
            float a = h[4 * nt],     b = h[4 * nt + 1];
            float c = h[4 * nt + 2], d = h[4 * nt + 3];
            float2 lo = {cst * a / (1.f + __expf(-a)), cst * b / (1.f + __expf(-b))};
            float2 hi = {cst * c / (1.f + __expf(-c)), cst * d / (1.f + __expf(-d))};
            *(float2*)&A0[r4 * TSTR + nt * 8 + 2 * m4]       = lo;
            *(float2*)&A0[(r4 + 8) * TSTR + nt * 8 + 2 * m4] = hi;
        }
        __syncwarp();
        float wt[64];
#pragma unroll
        for (int i = 0; i < 64; i++) wt[i] = 0.f;
        gemm16g<16>(wt, A0, wm3g, r4, m4, lane);
        __syncwarp();

        // ---- stage x1 -> s0 (A0), s1k (A1..A3), fp32 ----
        for (int rr = 0; rr < 16; rr++) {
            float4 va = ((const float4*)x1a)[(base + rr) * 32 + lane];
            float4 vb = ((const float4*)x1b)[(base + rr) * 32 + lane];
            if (lane < 8) {
                *(float4*)&A0[rr * TSTR + 4 * lane]      = va;
                *(float4*)&A0[rr * TSTR + 32 + 4 * lane] = vb;
            } else {
                int f = 4 * lane - 32;
                float av[4] = {va.x, va.y, va.z, va.w};
                float bv[4] = {vb.x, vb.y, vb.z, vb.w};
#pragma unroll
                for (int q = 0; q < 4; q++) {
                    int u = (f + q) / 3, k = (f + q) % 3;
                    float* Tk = (k == 0) ? A1 : ((k == 1) ? A2 : A3);
                    Tk[rr * TSTR + u]      = av[q];
                    Tk[rr * TSTR + 32 + u] = bv[q];
                }
            }
        }
        __syncwarp();

        const float y0A = Yt[4 * r4],        y0B = Yt[4 * (r4 + 8)];
        const float yA1 = Yt[4 * r4 + 1],    yB1 = Yt[4 * (r4 + 8) + 1];
        const float yA2 = Yt[4 * r4 + 2],    yB2 = Yt[4 * (r4 + 8) + 2];
        const float yA3 = Yt[4 * r4 + 3],    yB3 = Yt[4 * (r4 + 8) + 3];

        // ---- G4/G5: R0 = s0@w0, Pp = s0@w2 (shared A frags) ----
        float R0[16], Pp[16], R1[16];
#pragma unroll
        for (int i = 0; i < 16; i++) { R0[i] = 0.f; Pp[i] = 0.f; R1[i] = 0.f; }
#pragma unroll
        for (int k8 = 0; k8 < 8; k8++) {
            const float* ap = A0 + r4 * TSTR + k8 * 8 + m4;
            u32 h0, l0, h1, l1, h2, l2, h3, l3;
            split2(ap[0], h0, l0);
            split2(ap[8 * TSTR], h1, l1);
            split2(ap[4], h2, l2);
            split2(ap[8 * TSTR + 4], h3, l3);
            const float* w0p = smem + FB_W0 + k8 * 4 * 64 + 2 * lane;
            const float* w2p = smem + FB_W2 + k8 * 4 * 64 + 2 * lane;
#pragma unroll
            for (int nt = 0; nt < 4; nt++) {
                uint2 b0 = *(const uint2*)(w0p + nt * 64);
                mma_t(R0 + 4 * nt, h0, h1, h2, h3, b0.x, b0.y);
                mma_t(R0 + 4 * nt, l0, l1, l2, l3, b0.x, b0.y);
                uint2 b2 = *(const uint2*)(w2p + nt * 64);
                mma_t(Pp + 4 * nt, h0, h1, h2, h3, b2.x, b2.y);
                mma_t(Pp + 4 * nt, l0, l1, l2, l3, b2.x, b2.y);
            }
        }

        // ---- G6: R1 = t1@w1, t1 frags built on the fly ----
#pragma unroll
        for (int k8 = 0; k8 < 8; k8++) {
            int o = r4 * TSTR + k8 * 8 + m4;
            float t0 = A1[o] * yA1 + A2[o] * yA2 + A3[o] * yA3;
            float t2 = A1[o + 4] * yA1 + A2[o + 4] * yA2 + A3[o + 4] * yA3;
            float t1v = A1[o + 8 * TSTR] * yB1 + A2[o + 8 * TSTR] * yB2 + A3[o + 8 * TSTR] * yB3;
            float t3 = A1[o + 8 * TSTR + 4] * yB1 + A2[o + 8 * TSTR + 4] * yB2 + A3[o + 8 * TSTR + 4] * yB3;
            u32 h0, l0, h1, l1, h2, l2, h3, l3;
            split2(t0, h0, l0); split2(t1v, h1, l1);
            split2(t2, h2, l2); split2(t3, h3, l3);
            const float* w1p = smem + FB_W1 + k8 * 4 * 64 + 2 * lane;
#pragma unroll
            for (int nt = 0; nt < 4; nt++) {
                uint2 b = *(const uint2*)(w1p + nt * 64);
                mma_t(R1 + 4 * nt, h0, h1, h2, h3, b.x, b.y);
                mma_t(R1 + 4 * nt, l0, l1, l2, l3, b.x, b.y);
            }
        }
        __syncwarp();   // s0 reads done -> overlay m0 on A0

        // ---- m0 build -> A0 ----
#pragma unroll
        for (int nt = 0; nt < 4; nt++) {
            A0[r4 * TSTR + nt * 8 + 2 * m4]           = y0A * R0[4 * nt]     * wt[4 * nt];
            A0[r4 * TSTR + nt * 8 + 2 * m4 + 1]       = y0A * R0[4 * nt + 1] * wt[4 * nt + 1];
            A0[(r4 + 8) * TSTR + nt * 8 + 2 * m4]     = y0B * R0[4 * nt + 2] * wt[4 * nt + 2];
            A0[(r4 + 8) * TSTR + nt * 8 + 2 * m4 + 1] = y0B * R0[4 * nt + 3] * wt[4 * nt + 3];
            int wi = 4 * (nt + 4);
            A0[r4 * TSTR + 32 + nt * 8 + 2 * m4]           = R1[4 * nt]     * wt[wi];
            A0[r4 * TSTR + 32 + nt * 8 + 2 * m4 + 1]       = R1[4 * nt + 1] * wt[wi + 1];
            A0[(r4 + 8) * TSTR + 32 + nt * 8 + 2 * m4]     = R1[4 * nt + 2] * wt[wi + 2];
            A0[(r4 + 8) * TSTR + 32 + nt * 8 + 2 * m4 + 1] = R1[4 * nt + 3] * wt[wi + 3];
        }

        // ---- G7: Qk = s1k@w3 (B shared across k) ----
        float Q[48];
#pragma unroll
        for (int i = 0; i < 48; i++) Q[i] = 0.f;
#pragma unroll
        for (int k8 = 0; k8 < 8; k8++) {
            u32 H[3][4], L[3][4];
#pragma unroll
            for (int k = 0; k < 3; k++) {
                const float* Tk = (k == 0) ? A1 : ((k == 1) ? A2 : A3);
                int o = r4 * TSTR + k8 * 8 + m4;
                split2(Tk[o], H[k][0], L[k][0]);
                split2(Tk[o + 8 * TSTR], H[k][1], L[k][1]);
                split2(Tk[o + 4], H[k][2], L[k][2]);
                split2(Tk[o + 8 * TSTR + 4], H[k][3], L[k][3]);
            }
            const float* w3p = smem + FB_W3 + k8 * 4 * 64 + 2 * lane;
#pragma unroll
            for (int nt = 0; nt < 4; nt++) {
                uint2 b = *(const uint2*)(w3p + nt * 64);
#pragma unroll
                for (int k = 0; k < 3; k++) {
                    mma_t(Q + 16 * k + 4 * nt, H[k][0], H[k][1], H[k][2], H[k][3], b.x, b.y);
                    mma_t(Q + 16 * k + 4 * nt, L[k][0], L[k][1], L[k][2], L[k][3], b.x, b.y);
                }
            }
        }
        __syncwarp();   // s1 reads done -> overlay m1k

        // ---- m1k build -> A1..A3 ----
#pragma unroll
        for (int k = 0; k < 3; k++) {
            float* Tk = (k == 0) ? A1 : ((k == 1) ? A2 : A3);
            float ykA = (k == 0) ? yA1 : ((k == 1) ? yA2 : yA3);
            float ykB = (k == 0) ? yB1 : ((k == 1) ? yB2 : yB3);
#pragma unroll
            for (int nt = 0; nt < 4; nt++) {
                int wi = 4 * (nt + 8), wj = 4 * (nt + 12);
                Tk[r4 * TSTR + nt * 8 + 2 * m4]           = ykA * Pp[4 * nt]     * wt[wi];
                Tk[r4 * TSTR + nt * 8 + 2 * m4 + 1]       = ykA * Pp[4 * nt + 1] * wt[wi + 1];
                Tk[(r4 + 8) * TSTR + nt * 8 + 2 * m4]     = ykB * Pp[4 * nt + 2] * wt[wi + 2];
                Tk[(r4 + 8) * TSTR + nt * 8 + 2 * m4 + 1] = ykB * Pp[4 * nt + 3] * wt[wi + 3];
                Tk[r4 * TSTR + 32 + nt * 8 + 2 * m4]           = y0A * Q[16 * k + 4 * nt]     * wt[wj];
                Tk[r4 * TSTR + 32 + nt * 8 + 2 * m4 + 1]       = y0A * Q[16 * k + 4 * nt + 1] * wt[wj + 1];
                Tk[(r4 + 8) * TSTR + 32 + nt * 8 + 2 * m4]     = y0B * Q[16 * k + 4 * nt + 2] * wt[wj + 2];
                Tk[(r4 + 8) * TSTR + 32 + nt * 8 + 2 * m4 + 1] = y0B * Q[16 * k + 4 * nt + 3] * wt[wj + 3];
            }
        }
        __syncwarp();

        // ---- G8: O0 = m0@WA ; G9: Ok = m1k@WB (B shared) ----
        float O0[16];
#pragma unroll
        for (int i = 0; i < 16; i++) O0[i] = 0.f;
        gemm16s<4>(O0, A0, smem + FB_WA, r4, m4, lane);

        float O[48];
#pragma unroll
        for (int i = 0; i < 48; i++) O[i] = 0.f;
#pragma unroll
        for (int k8 = 0; k8 < 8; k8++) {
            u32 H[3][4], L[3][4];
#pragma unroll
            for (int k = 0; k < 3; k++) {
                const float* Tk = (k == 0) ? A1 : ((k == 1) ? A2 : A3);
                int o = r4 * TSTR + k8 * 8 + m4;
                split2(Tk[o], H[k][0], L[k][0]);
                split2(Tk[o + 8 * TSTR], H[k][1], L[k][1]);
                split2(Tk[o + 4], H[k][2], L[k][2]);
                split2(Tk[o + 8 * TSTR + 4], H[k][3], L[k][3]);
            }
            const float* wbp = smem + FB_WB + k8 * 4 * 64 + 2 * lane;
#pragma unroll
            for (int nt = 0; nt < 4; nt++) {
                uint2 b = *(const uint2*)(wbp + nt * 64);
#pragma unroll
                for (int k = 0; k < 3; k++) {
                    mma_t(O + 16 * k + 4 * nt, H[k][0], H[k][1], H[k][2], H[k][3], b.x, b.y);
                    mma_t(O + 16 * k + 4 * nt, L[k][0], L[k][1], L[k][2], L[k][3], b.x, b.y);
                }
            }
        }
        __syncwarp();   // m reads done -> overlay out staging on A0/A1

        // ---- stage outputs (OB = A0, stride OSTR) ----
        float* OB = A0;
#pragma unroll
        for (int nt = 0; nt < 4; nt++) {
            int u = nt * 8 + 2 * m4;
            OB[r4 * OSTR + u]           = O0[4 * nt];
            OB[r4 * OSTR + u + 1]       = O0[4 * nt + 1];
            OB[(r4 + 8) * OSTR + u]     = O0[4 * nt + 2];
            OB[(r4 + 8) * OSTR + u + 1] = O0[4 * nt + 3];
#pragma unroll
            for (int k = 0; k < 3; k++) {
                int c = 32 + 3 * u + k;
                OB[r4 * OSTR + c]           = O[16 * k + 4 * nt];
                OB[r4 * OSTR + c + 3]       = O[16 * k + 4 * nt + 1];
                OB[(r4 + 8) * OSTR + c]     = O[16 * k + 4 * nt + 2];
                OB[(r4 + 8) * OSTR + c + 3] = O[16 * k + 4 * nt + 3];
            }
        }
        __syncwarp();
#pragma unroll
        for (int rr = 0; rr < 16; rr++)
            ((float4*)out)[(base + rr) * 32 + lane] = *(const float4*)&OB[rr * OSTR + 4 * lane];
        __syncwarp();
    }
}

// ---------------- launch ----------------
extern "C" void kernel_launch(void* const* d_in, const int* in_sizes, int n_in,
                              void* d_out, int out_size) {
    const float* x1a     = (const float*)d_in[0];
    const float* x1b     = (const float*)d_in[1];
    const float* x2      = (const float*)d_in[2];
    const float* scalars = (const float*)d_in[3];
    const float* w0      = (const float*)d_in[4];
    const float* w1      = (const float*)d_in[5];
    const float* w2      = (const float*)d_in[6];
    const float* w3      = (const float*)d_in[7];
    const float* Wl0     = (const float*)d_in[8];
    const float* Wl1     = (const float*)d_in[9];
    const float* Wm1     = (const float*)d_in[10];
    const float* Wm2     = (const float*)d_in[11];
    const float* Wm3     = (const float*)d_in[12];
    const float* Wf0     = (const float*)d_in[13];
    const float* Wf1     = (const float*)d_in[14];
    int n = in_sizes[0] / 128;

    cudaFuncSetAttribute(tp_mma_kernel, cudaFuncAttributeMaxDynamicSharedMemorySize, SMEM_BYTES);

    prep_kernel<<<112, 256>>>(w0, w1, w2, w3, Wl0, Wl1, Wm1, Wm2, Wm3, Wf0, Wf1);
    tp_mma_kernel<<<148, 256, SMEM_BYTES>>>(x1a, x1b, (const float4*)x2, scalars,
                                            (float*)d_out, n);
}

// round 8
// speedup vs baseline: 1.6113x; 1.0524x over previous
#include <cuda_runtime.h>
#include <math.h>

typedef unsigned int u32;

// weight buffer (floats): six small matrices -> smem; Wm1/Wm2/Wm3 stay in GLOBAL (L2-hot)
#define FB_W0  0
#define FB_W1  2048
#define FB_W2  4096
#define FB_W3  6144
#define FB_WA  8192
#define FB_WB  10240
#define FB_SM  12288               // floats copied to smem
#define FB_WM1 12288
#define FB_WM2 16384
#define FB_WM3 20480
#define FB_TOT 28672

#define NWARP  10
#define TSTR   68
#define TFL    (16 * TSTR)          // 1088
#define OSTR   132
#define ARENA  (4 * TFL)            // 4352 floats; Yt lives in A3 column padding
#define SMEM_FLOATS (FB_SM + NWARP * ARENA)    // 12288 + 43520 = 55808
#define SMEM_BYTES  (SMEM_FLOATS * 4)          // 223232

__device__ float g_cst;
__device__ float g_wbuf[FB_TOT];

__device__ __forceinline__ u32 tf32(float f) {
    u32 u; asm("cvt.rna.tf32.f32 %0,%1;" : "=r"(u) : "f"(f)); return u;
}
__device__ __forceinline__ void split2(float x, u32& h, u32& l) {
    h = tf32(x);
    l = tf32(x - __uint_as_float(h));
}
__device__ __forceinline__ void mma_t(float* d, u32 a0, u32 a1, u32 a2, u32 a3,
                                      u32 b0, u32 b1) {
    asm("mma.sync.aligned.m16n8k8.row.col.f32.tf32.tf32.f32 "
        "{%0,%1,%2,%3},{%4,%5,%6,%7},{%8,%9},{%0,%1,%2,%3};"
        : "+f"(d[0]), "+f"(d[1]), "+f"(d[2]), "+f"(d[3])
        : "r"(a0), "r"(a1), "r"(a2), "r"(a3), "r"(b0), "r"(b1));
}

// acc[4*NT] += T[16x64] @ W(smem) ; A hi/lo-split, W fragment-linear single tf32
template<int NT>
__device__ __forceinline__ void gemm16s(float* acc, const float* T, const float* W,
                                        int r4, int m4, int lane) {
#pragma unroll
    for (int k8 = 0; k8 < 8; k8++) {
        const float* ap = T + r4 * TSTR + k8 * 8 + m4;
        u32 h0, l0, h1, l1, h2, l2, h3, l3;
        split2(ap[0], h0, l0);
        split2(ap[8 * TSTR], h1, l1);
        split2(ap[4], h2, l2);
        split2(ap[8 * TSTR + 4], h3, l3);
        const float* wp = W + k8 * NT * 64 + 2 * lane;
#pragma unroll
        for (int nt = 0; nt < NT; nt++) {
            uint2 b = *(const uint2*)(wp + nt * 64);
            mma_t(acc + 4 * nt, h0, h1, h2, h3, b.x, b.y);
            mma_t(acc + 4 * nt, l0, l1, l2, l3, b.x, b.y);
        }
    }
}

// same but W read from GLOBAL via __ldg (Wm1/Wm2/Wm3, L2-hot)
template<int NT>
__device__ __forceinline__ void gemm16g(float* acc, const float* T, const float* W,
                                        int r4, int m4, int lane) {
#pragma unroll
    for (int k8 = 0; k8 < 8; k8++) {
        const float* ap = T + r4 * TSTR + k8 * 8 + m4;
        u32 h0, l0, h1, l1, h2, l2, h3, l3;
        split2(ap[0], h0, l0);
        split2(ap[8 * TSTR], h1, l1);
        split2(ap[4], h2, l2);
        split2(ap[8 * TSTR + 4], h3, l3);
        const float* wp = W + k8 * NT * 64 + 2 * lane;
#pragma unroll
        for (int nt = 0; nt < NT; nt++) {
            uint2 b = __ldg((const uint2*)(wp + nt * 64));
            mma_t(acc + 4 * nt, h0, h1, h2, h3, b.x, b.y);
            mma_t(acc + 4 * nt, l0, l1, l2, l3, b.x, b.y);
        }
    }
}

// ---------------- prep ----------------
__global__ void prep_kernel(const float* __restrict__ w0, const float* __restrict__ w1,
                            const float* __restrict__ w2, const float* __restrict__ w3,
                            const float* __restrict__ Wl0, const float* __restrict__ Wl1,
                            const float* __restrict__ Wm1, const float* __restrict__ Wm2,
                            const float* __restrict__ Wm3,
                            const float* __restrict__ Wf0, const float* __restrict__ Wf1) {
    if (blockIdx.x == 0) {
        const int   N = 20000;
        const float h = 24.0f / 20000.0f;
        float local = 0.0f;
        for (int i = threadIdx.x; i <= N; i += blockDim.x) {
            float z   = -12.0f + h * (float)i;
            float s   = z / (1.0f + __expf(-z));
            float phi = __expf(-0.5f * z * z) * 0.3989422804014327f;
            float f   = s * s * phi;
            if (i == 0 || i == N) f *= 0.5f;
            local += f;
        }
        __shared__ float red[256];
        red[threadIdx.x] = local;
        __syncthreads();
        for (int s = 128; s > 0; s >>= 1) {
            if (threadIdx.x < s) red[threadIdx.x] += red[threadIdx.x + s];
            __syncthreads();
        }
        if (threadIdx.x == 0) g_cst = rsqrtf(red[0] * h);
    }

    int tid = blockIdx.x * blockDim.x + threadIdx.x;
    if (tid >= FB_TOT) return;
    const float INV_S3 = 0.57735026918962576f;
    const float WSCALE = 0.125f * 0.125f * 0.17677669529663687f;

    int mbase, N;
    if (tid < FB_SM)           { mbase = (tid / 2048) * 2048; N = 32; }
    else if (tid < FB_WM2)     { mbase = FB_WM1; N = 64; }
    else if (tid < FB_WM3)     { mbase = FB_WM2; N = 64; }
    else                       { mbase = FB_WM3; N = 128; }
    int idx = tid - mbase;
    int g = idx >> 6, pos = idx & 63, l = pos >> 1, hh = pos & 1;
    int ntn = N >> 3, k8 = g / ntn, n8 = g % ntn;
    int row = k8 * 8 + (l & 3) + 4 * hh;   // K index
    int col = n8 * 8 + (l >> 2);           // N index

    float v;
    if (tid < 2048)            v = w0[row * 32 + col];
    else if (tid < 4096)       v = w1[row * 32 + col] * INV_S3;
    else if (tid < 6144)       v = w2[row * 32 + col];
    else if (tid < 8192)       v = w3[row * 32 + col];
    else if (tid < FB_SM) {
        const float* L = (tid < 10240) ? Wl0 : Wl1;
        const float* F = (tid < 10240) ? Wf0 : Wf1;
        float acc = 0.0f;
        for (int w = 0; w < 32; w++) acc = fmaf(L[row * 32 + w], F[w * 32 + col], acc);
        v = acc * WSCALE;
    }
    else if (tid < FB_WM2)     v = Wm1[row * 64 + col] * 0.125f;
    else if (tid < FB_WM3)     v = Wm2[row * 64 + col] * 0.125f;
    else                       v = Wm3[row * 128 + col] * 0.125f;
    g_wbuf[tid] = __uint_as_float(tf32(v));
}

// ---------------- main ----------------
__global__ __launch_bounds__(32 * NWARP, 1)
void tp_mma_kernel(const float* __restrict__ x1a, const float* __restrict__ x1b,
                   const float4* __restrict__ x2, const float* __restrict__ scalars,
                   float* __restrict__ out, int nrows) {
    extern __shared__ float smem[];
    {
        const float4* src = (const float4*)g_wbuf;
        float4* dst = (float4*)smem;
        for (int i = threadIdx.x; i < FB_SM / 4; i += 32 * NWARP) dst[i] = src[i];
    }
    __syncthreads();
    const float cst = g_cst;
    const float* wm1g = g_wbuf + FB_WM1;
    const float* wm2g = g_wbuf + FB_WM2;
    const float* wm3g = g_wbuf + FB_WM3;

    const int lane = threadIdx.x & 31, wid = threadIdx.x >> 5;
    const int r4 = lane >> 2, m4 = lane & 3;

    float* A0 = smem + FB_SM + wid * ARENA;
    float* A1 = A0 + TFL;
    float* A2 = A1 + TFL;
    float* A3 = A2 + TFL;
    // Yt lives in A3 column padding: row rr -> A3[rr*TSTR + 64 .. 68)

    const int gw = blockIdx.x * NWARP + wid, gwn = gridDim.x * NWARP;
    const int ntiles = nrows >> 4;

    for (int t = gw; t < ntiles; t += gwn) {
        const int base = t * 16;

        // ---- stage scalars (fp32) + y (into A3 padding) ----
#pragma unroll
        for (int j = 0; j < 8; j++) {
            int row = r4 + 8 * (j & 1), f4 = m4 + 4 * (j >> 1);
            *(float4*)&A0[row * TSTR + 4 * f4] =
                ((const float4*)scalars)[(base + row) * 16 + f4];
        }
        if (lane < 16) *(float4*)&A3[lane * TSTR + 64] = x2[base + lane];
        __syncwarp();

        // ---- MLP GEMM1 -> silu -> GEMM2 -> silu -> GEMM3 (weights via L2) ----
        float h[32];
#pragma unroll
        for (int i = 0; i < 32; i++) h[i] = 0.f;
        gemm16g<8>(h, A0, wm1g, r4, m4, lane);
        __syncwarp();
#pragma unroll
        for (int nt = 0; nt < 8; nt++) {
            float a = h[4 * nt],     b = h[4 * nt + 1];
            float c = h[4 * nt + 2], d = h[4 * nt + 3];
            float2 lo = {cst * a / (1.f + __expf(-a)), cst * b / (1.f + __expf(-b))};
            float2 hi = {cst * c / (1.f + __expf(-c)), cst * d / (1.f + __expf(-d))};
            *(float2*)&A0[r4 * TSTR + nt * 8 + 2 * m4]       = lo;
            *(float2*)&A0[(r4 + 8) * TSTR + nt * 8 + 2 * m4] = hi;
        }
        __syncwarp();
#pragma unroll
        for (int i = 0; i < 32; i++) h[i] = 0.f;
        gemm16g<8>(h, A0, wm2g, r4, m4, lane);
        __syncwarp();
#pragma unroll
        for (int nt = 0; nt < 8; nt++) {
            float a = h[4 * nt],     b = h[4 * nt + 1];
            float c = h[4 * nt + 2], d = h[4 * nt + 3];
            float2 lo = {cst * a / (1.f + __expf(-a)), cst * b / (1.f + __expf(-b))};
            float2 hi = {cst * c / (1.f + __expf(-c)), cst * d / (1.f + __expf(-d))};
            *(float2*)&A0[r4 * TSTR + nt * 8 + 2 * m4]       = lo;
            *(float2*)&A0[(r4 + 8) * TSTR + nt * 8 + 2 * m4] = hi;
        }
        __syncwarp();
        float wt[64];
#pragma unroll
        for (int i = 0; i < 64; i++) wt[i] = 0.f;
        gemm16g<16>(wt, A0, wm3g, r4, m4, lane);
        __syncwarp();

        // ---- stage x1 -> s0 (A0), s1k (A1..A3), fp32 ----
        for (int rr = 0; rr < 16; rr++) {
            float4 va = ((const float4*)x1a)[(base + rr) * 32 + lane];
            float4 vb = ((const float4*)x1b)[(base + rr) * 32 + lane];
            if (lane < 8) {
                *(float4*)&A0[rr * TSTR + 4 * lane]      = va;
                *(float4*)&A0[rr * TSTR + 32 + 4 * lane] = vb;
            } else {
                int f = 4 * lane - 32;
                float av[4] = {va.x, va.y, va.z, va.w};
                float bv[4] = {vb.x, vb.y, vb.z, vb.w};
#pragma unroll
                for (int q = 0; q < 4; q++) {
                    int u = (f + q) / 3, k = (f + q) % 3;
                    float* Tk = (k == 0) ? A1 : ((k == 1) ? A2 : A3);
                    Tk[rr * TSTR + u]      = av[q];
                    Tk[rr * TSTR + 32 + u] = bv[q];
                }
            }
        }
        __syncwarp();

        const float y0A = A3[r4 * TSTR + 64],       y0B = A3[(r4 + 8) * TSTR + 64];
        const float yA1 = A3[r4 * TSTR + 65],       yB1 = A3[(r4 + 8) * TSTR + 65];
        const float yA2 = A3[r4 * TSTR + 66],       yB2 = A3[(r4 + 8) * TSTR + 66];
        const float yA3 = A3[r4 * TSTR + 67],       yB3 = A3[(r4 + 8) * TSTR + 67];

        // ---- G4/G5: R0 = s0@w0, Pp = s0@w2 (shared A frags) ----
        float R0[16], Pp[16], R1[16];
#pragma unroll
        for (int i = 0; i < 16; i++) { R0[i] = 0.f; Pp[i] = 0.f; R1[i] = 0.f; }
#pragma unroll
        for (int k8 = 0; k8 < 8; k8++) {
            const float* ap = A0 + r4 * TSTR + k8 * 8 + m4;
            u32 h0, l0, h1, l1, h2, l2, h3, l3;
            split2(ap[0], h0, l0);
            split2(ap[8 * TSTR], h1, l1);
            split2(ap[4], h2, l2);
            split2(ap[8 * TSTR + 4], h3, l3);
            const float* w0p = smem + FB_W0 + k8 * 4 * 64 + 2 * lane;
            const float* w2p = smem + FB_W2 + k8 * 4 * 64 + 2 * lane;
#pragma unroll
            for (int nt = 0; nt < 4; nt++) {
                uint2 b0 = *(const uint2*)(w0p + nt * 64);
                mma_t(R0 + 4 * nt, h0, h1, h2, h3, b0.x, b0.y);
                mma_t(R0 + 4 * nt, l0, l1, l2, l3, b0.x, b0.y);
                uint2 b2 = *(const uint2*)(w2p + nt * 64);
                mma_t(Pp + 4 * nt, h0, h1, h2, h3, b2.x, b2.y);
                mma_t(Pp + 4 * nt, l0, l1, l2, l3, b2.x, b2.y);
            }
        }

        // ---- G6: R1 = t1@w1, t1 frags built on the fly ----
#pragma unroll
        for (int k8 = 0; k8 < 8; k8++) {
            int o = r4 * TSTR + k8 * 8 + m4;
            float t0 = A1[o] * yA1 + A2[o] * yA2 + A3[o] * yA3;
            float t2 = A1[o + 4] * yA1 + A2[o + 4] * yA2 + A3[o + 4] * yA3;
            float t1v = A1[o + 8 * TSTR] * yB1 + A2[o + 8 * TSTR] * yB2 + A3[o + 8 * TSTR] * yB3;
            float t3 = A1[o + 8 * TSTR + 4] * yB1 + A2[o + 8 * TSTR + 4] * yB2 + A3[o + 8 * TSTR + 4] * yB3;
            u32 h0, l0, h1, l1, h2, l2, h3, l3;
            split2(t0, h0, l0); split2(t1v, h1, l1);
            split2(t2, h2, l2); split2(t3, h3, l3);
            const float* w1p = smem + FB_W1 + k8 * 4 * 64 + 2 * lane;
#pragma unroll
            for (int nt = 0; nt < 4; nt++) {
                uint2 b = *(const uint2*)(w1p + nt * 64);
                mma_t(R1 + 4 * nt, h0, h1, h2, h3, b.x, b.y);
                mma_t(R1 + 4 * nt, l0, l1, l2, l3, b.x, b.y);
            }
        }
        __syncwarp();   // s0 reads done -> overlay m0 on A0

        // ---- m0 build -> A0 ----
#pragma unroll
        for (int nt = 0; nt < 4; nt++) {
            A0[r4 * TSTR + nt * 8 + 2 * m4]           = y0A * R0[4 * nt]     * wt[4 * nt];
            A0[r4 * TSTR + nt * 8 + 2 * m4 + 1]       = y0A * R0[4 * nt + 1] * wt[4 * nt + 1];
            A0[(r4 + 8) * TSTR + nt * 8 + 2 * m4]     = y0B * R0[4 * nt + 2] * wt[4 * nt + 2];
            A0[(r4 + 8) * TSTR + nt * 8 + 2 * m4 + 1] = y0B * R0[4 * nt + 3] * wt[4 * nt + 3];
            int wi = 4 * (nt + 4);
            A0[r4 * TSTR + 32 + nt * 8 + 2 * m4]           = R1[4 * nt]     * wt[wi];
            A0[r4 * TSTR + 32 + nt * 8 + 2 * m4 + 1]       = R1[4 * nt + 1] * wt[wi + 1];
            A0[(r4 + 8) * TSTR + 32 + nt * 8 + 2 * m4]     = R1[4 * nt + 2] * wt[wi + 2];
            A0[(r4 + 8) * TSTR + 32 + nt * 8 + 2 * m4 + 1] = R1[4 * nt + 3] * wt[wi + 3];
        }

        // ---- G7: Qk = s1k@w3 (B shared across k) ----
        float Q[48];
#pragma unroll
        for (int i = 0; i < 48; i++) Q[i] = 0.f;
#pragma unroll
        for (int k8 = 0; k8 < 8; k8++) {
            u32 H[3][4], L[3][4];
#pragma unroll
            for (int k = 0; k < 3; k++) {
                const float* Tk = (k == 0) ? A1 : ((k == 1) ? A2 : A3);
                int o = r4 * TSTR + k8 * 8 + m4;
                split2(Tk[o], H[k][0], L[k][0]);
                split2(Tk[o + 8 * TSTR], H[k][1], L[k][1]);
                split2(Tk[o + 4], H[k][2], L[k][2]);
                split2(Tk[o + 8 * TSTR + 4], H[k][3], L[k][3]);
            }
            const float* w3p = smem + FB_W3 + k8 * 4 * 64 + 2 * lane;
#pragma unroll
            for (int nt = 0; nt < 4; nt++) {
                uint2 b = *(const uint2*)(w3p + nt * 64);
#pragma unroll
                for (int k = 0; k < 3; k++) {
                    mma_t(Q + 16 * k + 4 * nt, H[k][0], H[k][1], H[k][2], H[k][3], b.x, b.y);
                    mma_t(Q + 16 * k + 4 * nt, L[k][0], L[k][1], L[k][2], L[k][3], b.x, b.y);
                }
            }
        }
        __syncwarp();   // s1 reads done -> overlay m1k

        // ---- m1k build -> A1..A3 ----
#pragma unroll
        for (int k = 0; k < 3; k++) {
            float* Tk = (k == 0) ? A1 : ((k == 1) ? A2 : A3);
            float ykA = (k == 0) ? yA1 : ((k == 1) ? yA2 : yA3);
            float ykB = (k == 0) ? yB1 : ((k == 1) ? yB2 : yB3);
#pragma unroll
            for (int nt = 0; nt < 4; nt++) {
                int wi = 4 * (nt + 8), wj = 4 * (nt + 12);
                Tk[r4 * TSTR + nt * 8 + 2 * m4]           = ykA * Pp[4 * nt]     * wt[wi];
                Tk[r4 * TSTR + nt * 8 + 2 * m4 + 1]       = ykA * Pp[4 * nt + 1] * wt[wi + 1];
                Tk[(r4 + 8) * TSTR + nt * 8 + 2 * m4]     = ykB * Pp[4 * nt + 2] * wt[wi + 2];
                Tk[(r4 + 8) * TSTR + nt * 8 + 2 * m4 + 1] = ykB * Pp[4 * nt + 3] * wt[wi + 3];
                Tk[r4 * TSTR + 32 + nt * 8 + 2 * m4]           = y0A * Q[16 * k + 4 * nt]     * wt[wj];
                Tk[r4 * TSTR + 32 + nt * 8 + 2 * m4 + 1]       = y0A * Q[16 * k + 4 * nt + 1] * wt[wj + 1];
                Tk[(r4 + 8) * TSTR + 32 + nt * 8 + 2 * m4]     = y0B * Q[16 * k + 4 * nt + 2] * wt[wj + 2];
                Tk[(r4 + 8) * TSTR + 32 + nt * 8 + 2 * m4 + 1] = y0B * Q[16 * k + 4 * nt + 3] * wt[wj + 3];
            }
        }
        __syncwarp();

        // ---- G8: O0 = m0@WA ; G9: Ok = m1k@WB (B shared) ----
        float O0[16];
#pragma unroll
        for (int i = 0; i < 16; i++) O0[i] = 0.f;
        gemm16s<4>(O0, A0, smem + FB_WA, r4, m4, lane);

        float O[48];
#pragma unroll
        for (int i = 0; i < 48; i++) O[i] = 0.f;
#pragma unroll
        for (int k8 = 0; k8 < 8; k8++) {
            u32 H[3][4], L[3][4];
#pragma unroll
            for (int k = 0; k < 3; k++) {
                const float* Tk = (k == 0) ? A1 : ((k == 1) ? A2 : A3);
                int o = r4 * TSTR + k8 * 8 + m4;
                split2(Tk[o], H[k][0], L[k][0]);
                split2(Tk[o + 8 * TSTR], H[k][1], L[k][1]);
                split2(Tk[o + 4], H[k][2], L[k][2]);
                split2(Tk[o + 8 * TSTR + 4], H[k][3], L[k][3]);
            }
            const float* wbp = smem + FB_WB + k8 * 4 * 64 + 2 * lane;
#pragma unroll
            for (int nt = 0; nt < 4; nt++) {
                uint2 b = *(const uint2*)(wbp + nt * 64);
#pragma unroll
                for (int k = 0; k < 3; k++) {
                    mma_t(O + 16 * k + 4 * nt, H[k][0], H[k][1], H[k][2], H[k][3], b.x, b.y);
                    mma_t(O + 16 * k + 4 * nt, L[k][0], L[k][1], L[k][2], L[k][3], b.x, b.y);
                }
            }
        }
        __syncwarp();   // m reads done -> overlay out staging on A0/A1

        // ---- stage outputs (OB = A0, stride OSTR) ----
        float* OB = A0;
#pragma unroll
        for (int nt = 0; nt < 4; nt++) {
            int u = nt * 8 + 2 * m4;
            OB[r4 * OSTR + u]           = O0[4 * nt];
            OB[r4 * OSTR + u + 1]       = O0[4 * nt + 1];
            OB[(r4 + 8) * OSTR + u]     = O0[4 * nt + 2];
            OB[(r4 + 8) * OSTR + u + 1] = O0[4 * nt + 3];
#pragma unroll
            for (int k = 0; k < 3; k++) {
                int c = 32 + 3 * u + k;
                OB[r4 * OSTR + c]           = O[16 * k + 4 * nt];
                OB[r4 * OSTR + c + 3]       = O[16 * k + 4 * nt + 1];
                OB[(r4 + 8) * OSTR + c]     = O[16 * k + 4 * nt + 2];
                OB[(r4 + 8) * OSTR + c + 3] = O[16 * k + 4 * nt + 3];
            }
        }
        __syncwarp();
#pragma unroll
        for (int rr = 0; rr < 16; rr++)
            ((float4*)out)[(base + rr) * 32 + lane] = *(const float4*)&OB[rr * OSTR + 4 * lane];
        __syncwarp();
    }
}

// ---------------- launch ----------------
extern "C" void kernel_launch(void* const* d_in, const int* in_sizes, int n_in,
                              void* d_out, int out_size) {
    const float* x1a     = (const float*)d_in[0];
    const float* x1b     = (const float*)d_in[1];
    const float* x2      = (const float*)d_in[2];
    const float* scalars = (const float*)d_in[3];
    const float* w0      = (const float*)d_in[4];
    const float* w1      = (const float*)d_in[5];
    const float* w2      = (const float*)d_in[6];
    const float* w3      = (const float*)d_in[7];
    const float* Wl0     = (const float*)d_in[8];
    const float* Wl1     = (const float*)d_in[9];
    const float* Wm1     = (const float*)d_in[10];
    const float* Wm2     = (const float*)d_in[11];
    const float* Wm3     = (const float*)d_in[12];
    const float* Wf0     = (const float*)d_in[13];
    const float* Wf1     = (const float*)d_in[14];
    int n = in_sizes[0] / 128;

    cudaFuncSetAttribute(tp_mma_kernel, cudaFuncAttributeMaxDynamicSharedMemorySize, SMEM_BYTES);

    prep_kernel<<<112, 256>>>(w0, w1, w2, w3, Wl0, Wl1, Wm1, Wm2, Wm3, Wf0, Wf1);
    tp_mma_kernel<<<148, 32 * NWARP, SMEM_BYTES>>>(x1a, x1b, (const float4*)x2, scalars,
                                                   (float*)d_out, n);
}